// round 13
// baseline (speedup 1.0000x reference)
#include <cuda_runtime.h>

#define B_N 64
#define A_N 10647
#define G_N 50
#define C_N 9
#define NCHUNK 21
#define CH 512           // == NA*NTHR; 21*512 = 10752 >= 10647
#define NTHR 128
#define NA 4
#define NW (NTHR / 32)   // 4 warps per block

__device__ unsigned long long g_keys[B_N * NCHUNK * G_N];
__device__ float g_bce[B_N * NCHUNK];
__device__ float g_perimg[B_N];

__device__ __forceinline__ float clog(float x) { return fmaxf(__logf(x), -100.0f); }

// Kernel 1: per (batch, anchor-chunk): per-gt best-r anchor (r = inter/S, monotonic in IoU)
// packed key + partial bce0 sum. NTHR=128 halves per-block prologue count (measured win).
__global__ __launch_bounds__(NTHR, 11) void yolo_k1(const float* __restrict__ pred,
                                                    const float* __restrict__ bboxes,
                                                    const int* __restrict__ classes) {
    const int b = blockIdx.y, c = blockIdx.x;
    const int tid = threadIdx.x, lane = tid & 31, warp = tid >> 5;

    __shared__ float4 sgc[G_N];                  // compacted gt corners (LDS.128 per gt)
    __shared__ float sga[G_N];                   // compacted area_g + eps
    __shared__ int sgid[G_N];                    // compacted -> original gt id
    __shared__ int sval[G_N];
    __shared__ int scnt;
    __shared__ unsigned long long swk[G_N][NW];
    __shared__ float sbce[NW];

    if (tid == 0) scnt = 0;
    __syncthreads();

    if (tid < G_N) {
        int v = (classes[b * G_N + tid] != -1);
        sval[tid] = v;
        if (v) {
            const float* gb = bboxes + (b * G_N + tid) * 4;
            float x1 = gb[0], y1 = gb[1], x2 = gb[2], y2 = gb[3];
            float cx = (x1 + x2) * 0.5f, cy = (y1 + y2) * 0.5f;
            float w = x2 - x1, h = y2 - y1;
            float gx1 = cx - w * 0.5f, gy1 = cy - h * 0.5f;
            float gx2 = cx + w * 0.5f, gy2 = cy + h * 0.5f;
            int p = atomicAdd(&scnt, 1);         // order-independent: results keyed by sgid
            sgc[p] = make_float4(gx1, gy1, gx2, gy2);
            sga[p] = (gx2 - gx1) * (gy2 - gy1) + 1e-16f;  // ref arithmetic + eps pre-added
            sgid[p] = tid;
        }
    }
    __syncthreads();
    const int nv = scnt;

    const int base = c * CH;
    // Anchor data register-resident.
    float px1[NA], py1[NA], px2[NA], py2[NA], pap[NA];
    float bce = 0.0f;

#pragma unroll
    for (int i = 0; i < NA; i++) {
        int a = base + tid + i * NTHR;
        bool ok = a < A_N;                       // only the last chunk is ragged
        int al = ok ? a : 0;
        const float* row = pred + (long long)(b * A_N + al) * 14;   // 8B-aligned (56B rows)
        float2 p01 = *(const float2*)(row);
        float2 p23 = *(const float2*)(row + 2);
        float conf = row[4];
        float cx = p01.x, cy = p01.y, w = p23.x, h = p23.y;
        float x1 = cx - w * 0.5f, x2 = cx + w * 0.5f;
        float y1 = cy - h * 0.5f, y2 = cy + h * 0.5f;
        float ap = (x2 - x1) * (y2 - y1);
        if (!ok) { x1 = 3.0e38f; x2 = 3.0e38f; y1 = 3.0e38f; y2 = 3.0e38f; ap = 0.0f; }
        px1[i] = x1; px2[i] = x2; py1[i] = y1; py2[i] = y2; pap[i] = ap;
        if (ok) bce += -clog(1.0f - conf);
    }

    // Per-gt argmax of r = inter / (area_p + area_g + eps), monotonic in IoU.
    // ih unclamped: negative ih => r <= 0, never beats a true overlap; final fmax(br,0)
    // restores r>=0 (+0) so bit order == float order for the unsigned REDUX.
    // Index resolution: second REDUX (min over matching offsets) — exact smallest-index
    // tie-break (per-thread serial scan already keeps the smallest slot on ties).
    for (int j = 0; j < nv; j++) {
        float4 gq = sgc[j];                      // one LDS.128
        float age = sga[j];                      // one LDS.32
        float br = -1.0f;
        int bslot = 0;
#pragma unroll
        for (int i = 0; i < NA; i++) {
            float iw = fmaxf(fminf(px2[i], gq.z) - fmaxf(px1[i], gq.x), 0.0f);
            float ih = fminf(py2[i], gq.w) - fmaxf(py1[i], gq.y);   // no clamp
            float inter = iw * ih;
            float S = pap[i] + age;              // > 0 always
            float r = __fdividef(inter, S);      // MUFU.RCP + FMUL
            bool better = r > br;                // strict > keeps smallest slot
            br = fmaxf(br, r);
            bslot = better ? i : bslot;
        }
        br = fmaxf(br, 0.0f);
        unsigned rb = __float_as_uint(br);
        unsigned m = __reduce_max_sync(0xFFFFFFFFu, rb);
        unsigned offk = (rb == m) ? (unsigned)(tid + bslot * NTHR) : 0xFFFFFFFFu;
        unsigned moff = __reduce_min_sync(0xFFFFFFFFu, offk);   // smallest offset == smallest idx
        if (lane == 0)
            swk[sgid[j]][warp] = ((unsigned long long)m << 32)
                               | (unsigned)(0xFFFFFFFFu - (unsigned)(base + moff));
    }

    // Deterministic bce0 partial-sum reduction (fixed tree order).
#pragma unroll
    for (int s = 16; s; s >>= 1) bce += __shfl_xor_sync(0xFFFFFFFFu, bce, s);
    if (lane == 0) sbce[warp] = bce;
    __syncthreads();
    if (tid == 0) g_bce[b * NCHUNK + c] = (sbce[0] + sbce[1]) + (sbce[2] + sbce[3]);

    if (tid < G_N) {
        unsigned long long k = 0ULL;
        if (sval[tid]) {
            unsigned long long a0 = swk[tid][0], a1 = swk[tid][1];
            unsigned long long a2 = swk[tid][2], a3 = swk[tid][3];
            unsigned long long m0 = a0 > a1 ? a0 : a1;
            unsigned long long m1 = a2 > a3 ? a2 : a3;
            k = m0 > m1 ? m0 : m1;
        }
        g_keys[(b * NCHUNK + c) * G_N + tid] = k;
    }
}

// Kernel 2: per batch: combine chunk keys, gather best anchor row, per-gt loss -> per_img.
// All reductions via warp shuffles (fixed order, deterministic). No fence/atomic finalize —
// that pattern measured ~6us slower twice (R2, R12).
__global__ void yolo_k2(const float* __restrict__ pred,
                        const float* __restrict__ bboxes,
                        const int* __restrict__ classes) {
    const int b = blockIdx.x, tid = threadIdx.x;
    const int lane = tid & 31, warp = tid >> 5;
    __shared__ float stot;
    __shared__ float spart[2];
    __shared__ int shas[2];

    if (warp == 0) {
        float t = (lane < NCHUNK) ? g_bce[b * NCHUNK + lane] : 0.0f;
#pragma unroll
        for (int s = 16; s; s >>= 1) t += __shfl_xor_sync(0xFFFFFFFFu, t, s);
        if (lane == 0) stot = t;
    }
    __syncthreads();
    float tot0 = stot;

    float pg = 0.0f;
    int val = 0;
    if (tid < G_N) {
        int cls = classes[b * G_N + tid];
        val = (cls != -1);
        if (val) {
            unsigned long long k = 0ULL;
#pragma unroll
            for (int j = 0; j < NCHUNK; j++) {
                unsigned long long v = g_keys[(b * NCHUNK + j) * G_N + tid];
                k = v > k ? v : k;
            }
            unsigned aidx = 0xFFFFFFFFu - (unsigned)(k & 0xFFFFFFFFULL);
            const float* row = pred + (long long)(b * A_N + aidx) * 14;
            const float* gb = bboxes + (b * G_N + tid) * 4;
            float x1 = gb[0], y1 = gb[1], x2 = gb[2], y2 = gb[3];
            float gcx = (x1 + x2) * 0.5f, gcy = (y1 + y2) * 0.5f;
            float gw = x2 - x1, gh = y2 - y1;
            float d0 = row[0] - gcx, d1 = row[1] - gcy;
            float d2 = row[2] - gw,  d3 = row[3] - gh;
            float coord = 5.0f * ((d0 * d0 + d1 * d1) + (d2 * d2 + d3 * d3));
            float conf = row[4];
            float conf_obj = -clog(conf);
            float clsl = 0.0f;
#pragma unroll
            for (int cc = 0; cc < C_N; cc++) {
                float p = row[5 + cc];
                clsl += (cc == cls) ? -clog(p) : -clog(1.0f - p);
            }
            float bce0b = -clog(1.0f - conf);
            float noobj = 0.5f * (tot0 - bce0b);
            pg = (coord + conf_obj) + (clsl + noobj);
        }
    }
#pragma unroll
    for (int s = 16; s; s >>= 1) pg += __shfl_xor_sync(0xFFFFFFFFu, pg, s);
    unsigned hasw = __ballot_sync(0xFFFFFFFFu, val);
    if (lane == 0) { spart[warp] = pg; shas[warp] = hasw; }
    __syncthreads();

    if (tid == 0) {
        float s = spart[0] + spart[1];
        int has = shas[0] | shas[1];
        g_perimg[b] = has ? s : 0.5f * tot0;
    }
}

// Kernel 3: deterministic final sum (warp tree).
__global__ void yolo_k3(float* __restrict__ out) {
    const int tid = threadIdx.x, lane = tid & 31, warp = tid >> 5;
    __shared__ float sp[2];
    float v = g_perimg[tid];            // 64 threads, 64 batches
#pragma unroll
    for (int s = 16; s; s >>= 1) v += __shfl_xor_sync(0xFFFFFFFFu, v, s);
    if (lane == 0) sp[warp] = v;
    __syncthreads();
    if (tid == 0) out[0] = (sp[0] + sp[1]) / (float)B_N;
}

extern "C" void kernel_launch(void* const* d_in, const int* in_sizes, int n_in,
                              void* d_out, int out_size) {
    const float* pred    = (const float*)d_in[0];
    const float* bboxes  = (const float*)d_in[1];
    const int*   classes = (const int*)d_in[2];
    float* out = (float*)d_out;

    dim3 g1(NCHUNK, B_N);
    yolo_k1<<<g1, NTHR>>>(pred, bboxes, classes);
    yolo_k2<<<B_N, 64>>>(pred, bboxes, classes);
    yolo_k3<<<1, 64>>>(out);
}

// round 14
// speedup vs baseline: 1.0683x; 1.0683x over previous
#include <cuda_runtime.h>

#define B_N 64
#define A_N 10647
#define G_N 50
#define C_N 9
#define NCHUNK 42
#define CH 256           // == NA*NTHR
#define NTHR 64
#define NA 4
#define NW (NTHR / 32)   // 2 warps per block

__device__ unsigned long long g_keys[B_N * G_N * NCHUNK];   // [b][gt][chunk] (k2-coalesced)
__device__ float g_bce[B_N * NCHUNK];
__device__ float g_perimg[B_N];

__device__ __forceinline__ float clog(float x) { return fmaxf(__logf(x), -100.0f); }

// Kernel 1: per (batch, anchor-chunk): per-gt best-r anchor (r = inter/S, monotonic in IoU)
// packed key + partial bce0 sum. Geometry: R11 measured-best (NTHR=64, NA=4, one wave).
__global__ __launch_bounds__(NTHR, 20) void yolo_k1(const float* __restrict__ pred,
                                                    const float* __restrict__ bboxes,
                                                    const int* __restrict__ classes) {
    const int b = blockIdx.y, c = blockIdx.x;
    const int tid = threadIdx.x, lane = tid & 31, warp = tid >> 5;

    __shared__ float4 sgc[G_N];                  // compacted gt corners (LDS.128 per gt)
    __shared__ float sga[G_N];                   // compacted area_g + eps
    __shared__ int sgid[G_N];                    // compacted -> original gt id
    __shared__ int sval[G_N];
    __shared__ int scnt;
    __shared__ unsigned long long swk[G_N][NW];
    __shared__ float sbce[NW];

    if (tid == 0) scnt = 0;
    __syncthreads();

    if (tid < G_N) {
        int v = (classes[b * G_N + tid] != -1);
        sval[tid] = v;
        if (v) {
            const float* gb = bboxes + (b * G_N + tid) * 4;
            float x1 = gb[0], y1 = gb[1], x2 = gb[2], y2 = gb[3];
            float cx = (x1 + x2) * 0.5f, cy = (y1 + y2) * 0.5f;
            float w = x2 - x1, h = y2 - y1;
            float gx1 = cx - w * 0.5f, gy1 = cy - h * 0.5f;
            float gx2 = cx + w * 0.5f, gy2 = cy + h * 0.5f;
            int p = atomicAdd(&scnt, 1);         // order-independent: results keyed by sgid
            sgc[p] = make_float4(gx1, gy1, gx2, gy2);
            sga[p] = (gx2 - gx1) * (gy2 - gy1) + 1e-16f;  // ref arithmetic + eps pre-added
            sgid[p] = tid;
        }
    }
    __syncthreads();
    const int nv = scnt;

    const int base = c * CH;
    // Anchor data register-resident.
    float px1[NA], py1[NA], px2[NA], py2[NA], pap[NA];
    float bce = 0.0f;

#pragma unroll
    for (int i = 0; i < NA; i++) {
        int a = base + tid + i * NTHR;
        bool ok = a < A_N;                       // only the last chunk is ragged
        int al = ok ? a : 0;
        const float* row = pred + (long long)(b * A_N + al) * 14;   // 8B-aligned (56B rows)
        float2 p01 = *(const float2*)(row);
        float2 p23 = *(const float2*)(row + 2);
        float conf = row[4];
        float cx = p01.x, cy = p01.y, w = p23.x, h = p23.y;
        float x1 = cx - w * 0.5f, x2 = cx + w * 0.5f;
        float y1 = cy - h * 0.5f, y2 = cy + h * 0.5f;
        float ap = (x2 - x1) * (y2 - y1);
        if (!ok) { x1 = 3.0e38f; x2 = 3.0e38f; y1 = 3.0e38f; y2 = 3.0e38f; ap = 0.0f; }
        px1[i] = x1; px2[i] = x2; py1[i] = y1; py2[i] = y2; pap[i] = ap;
        if (ok) bce += -clog(1.0f - conf);
    }

    // Per-gt argmax of r = inter / (area_p + area_g + eps), monotonic in IoU.
    // ih unclamped (r<=0 never beats a true overlap; +0 clamp before the bit-ordered REDUX).
    // Post-hoc tree argmax: r[] kept in regs, 3-deep FMNMX tree + 3 selects AFTER the loop
    // (removes the per-pair FSETP/FMNMX/SEL chain). Tie semantics == serial strict-> scan.
    for (int j = 0; j < nv; j++) {
        float4 gq = sgc[j];                      // one LDS.128
        float age = sga[j];                      // one LDS.32
        float r[NA];
#pragma unroll
        for (int i = 0; i < NA; i++) {
            float iw = fmaxf(fminf(px2[i], gq.z) - fmaxf(px1[i], gq.x), 0.0f);
            float ih = fminf(py2[i], gq.w) - fmaxf(py1[i], gq.y);   // no clamp
            float inter = iw * ih;
            float S = pap[i] + age;              // > 0 always
            r[i] = __fdividef(inter, S);         // MUFU.RCP + FMUL
        }
        float m01 = fmaxf(r[0], r[1]);
        float m23 = fmaxf(r[2], r[3]);
        float br  = fmaxf(fmaxf(m01, m23), 0.0f);
        int s01 = (r[1] > r[0]) ? 1 : 0;         // tie -> lower slot
        int s23 = (r[3] > r[2]) ? 3 : 2;
        int bslot = (m23 > m01) ? s23 : s01;     // tie -> lower pair

        unsigned rb = __float_as_uint(br);       // br >= +0 -> bit order == float order
        unsigned m = __reduce_max_sync(0xFFFFFFFFu, rb);
        unsigned offk = (rb == m) ? (unsigned)(tid + bslot * NTHR) : 0xFFFFFFFFu;
        unsigned moff = __reduce_min_sync(0xFFFFFFFFu, offk);   // smallest offset == smallest idx
        if (lane == 0)
            swk[sgid[j]][warp] = ((unsigned long long)m << 32)
                               | (unsigned)(0xFFFFFFFFu - (unsigned)(base + moff));
    }

    // Deterministic bce0 partial-sum reduction (fixed tree order).
#pragma unroll
    for (int s = 16; s; s >>= 1) bce += __shfl_xor_sync(0xFFFFFFFFu, bce, s);
    if (lane == 0) sbce[warp] = bce;
    __syncthreads();
    if (tid == 0) g_bce[b * NCHUNK + c] = sbce[0] + sbce[1];

    if (tid < G_N) {
        unsigned long long k = 0ULL;
        if (sval[tid]) {
            unsigned long long a0 = swk[tid][0], a1 = swk[tid][1];
            k = a0 > a1 ? a0 : a1;
        }
        g_keys[(b * G_N + tid) * NCHUNK + c] = k;   // transposed: contiguous per (b, gt)
    }
}

// Kernel 2: per batch: combine chunk keys (coalesced), gather best anchor row,
// per-gt loss -> per_img. All reductions via warp shuffles.
__global__ void yolo_k2(const float* __restrict__ pred,
                        const float* __restrict__ bboxes,
                        const int* __restrict__ classes) {
    const int b = blockIdx.x, tid = threadIdx.x;
    const int lane = tid & 31, warp = tid >> 5;
    __shared__ float stot;
    __shared__ float spart[2];
    __shared__ int shas[2];

    if (warp == 0) {
        float t = (lane < NCHUNK) ? g_bce[b * NCHUNK + lane] : 0.0f;
        if (lane + 32 < NCHUNK) t += g_bce[b * NCHUNK + lane + 32];
#pragma unroll
        for (int s = 16; s; s >>= 1) t += __shfl_xor_sync(0xFFFFFFFFu, t, s);
        if (lane == 0) stot = t;
    }
    __syncthreads();
    float tot0 = stot;

    float pg = 0.0f;
    int val = 0;
    if (tid < G_N) {
        int cls = classes[b * G_N + tid];
        val = (cls != -1);
        if (val) {
            const unsigned long long* kp = &g_keys[(b * G_N + tid) * NCHUNK];
            unsigned long long k = 0ULL;
#pragma unroll
            for (int j = 0; j < NCHUNK; j++) {
                unsigned long long v = kp[j];    // contiguous 336B per thread
                k = v > k ? v : k;
            }
            unsigned aidx = 0xFFFFFFFFu - (unsigned)(k & 0xFFFFFFFFULL);
            const float* row = pred + (long long)(b * A_N + aidx) * 14;
            const float* gb = bboxes + (b * G_N + tid) * 4;
            float x1 = gb[0], y1 = gb[1], x2 = gb[2], y2 = gb[3];
            float gcx = (x1 + x2) * 0.5f, gcy = (y1 + y2) * 0.5f;
            float gw = x2 - x1, gh = y2 - y1;
            float d0 = row[0] - gcx, d1 = row[1] - gcy;
            float d2 = row[2] - gw,  d3 = row[3] - gh;
            float coord = 5.0f * ((d0 * d0 + d1 * d1) + (d2 * d2 + d3 * d3));
            float conf = row[4];
            float conf_obj = -clog(conf);
            float clsl = 0.0f;
#pragma unroll
            for (int cc = 0; cc < C_N; cc++) {
                float p = row[5 + cc];
                clsl += (cc == cls) ? -clog(p) : -clog(1.0f - p);
            }
            float bce0b = -clog(1.0f - conf);
            float noobj = 0.5f * (tot0 - bce0b);
            pg = (coord + conf_obj) + (clsl + noobj);
        }
    }
#pragma unroll
    for (int s = 16; s; s >>= 1) pg += __shfl_xor_sync(0xFFFFFFFFu, pg, s);
    unsigned hasw = __ballot_sync(0xFFFFFFFFu, val);
    if (lane == 0) { spart[warp] = pg; shas[warp] = hasw; }
    __syncthreads();

    if (tid == 0) {
        float s = spart[0] + spart[1];
        int has = shas[0] | shas[1];
        g_perimg[b] = has ? s : 0.5f * tot0;
    }
}

// Kernel 3: deterministic final sum (warp tree).
__global__ void yolo_k3(float* __restrict__ out) {
    const int tid = threadIdx.x, lane = tid & 31, warp = tid >> 5;
    __shared__ float sp[2];
    float v = g_perimg[tid];            // 64 threads, 64 batches
#pragma unroll
    for (int s = 16; s; s >>= 1) v += __shfl_xor_sync(0xFFFFFFFFu, v, s);
    if (lane == 0) sp[warp] = v;
    __syncthreads();
    if (tid == 0) out[0] = (sp[0] + sp[1]) / (float)B_N;
}

extern "C" void kernel_launch(void* const* d_in, const int* in_sizes, int n_in,
                              void* d_out, int out_size) {
    const float* pred    = (const float*)d_in[0];
    const float* bboxes  = (const float*)d_in[1];
    const int*   classes = (const int*)d_in[2];
    float* out = (float*)d_out;

    dim3 g1(NCHUNK, B_N);
    yolo_k1<<<g1, NTHR>>>(pred, bboxes, classes);
    yolo_k2<<<B_N, 64>>>(pred, bboxes, classes);
    yolo_k3<<<1, 64>>>(out);
}

// round 15
// speedup vs baseline: 1.1302x; 1.0580x over previous
#include <cuda_runtime.h>

#define B_N 64
#define A_N 10647
#define G_N 50
#define C_N 9
#define NCHUNK 42
#define CH 256           // == NA*NTHR
#define NTHR 64
#define NA 4
#define NWC (NCHUNK * 2) // 84 warp-chunks of 128 anchors each

__device__ unsigned long long g_rmax[B_N * G_N * NWC];  // [(b*G+g)*84 + wc] packed (m, ~wc)
__device__ float g_bce[B_N * NWC];
__device__ float g_perimg[B_N];

__device__ __forceinline__ float clog(float x) { return fmaxf(__logf(x), -100.0f); }

// Kernel 1: per (batch, chunk): for each valid gt, the WARP-LOCAL max of
// r = inter/(area_p + area_g + eps) (monotonic in IoU) -> one packed key per
// (gt, warp-chunk). NO index tracking, NO cross-warp combine: k2 re-derives the
// argmax index by rescanning only the winning 128-anchor warp-chunk.
__global__ __launch_bounds__(NTHR, 20) void yolo_k1(const float* __restrict__ pred,
                                                    const float* __restrict__ bboxes,
                                                    const int* __restrict__ classes) {
    const int b = blockIdx.y, c = blockIdx.x;
    const int tid = threadIdx.x, lane = tid & 31, warp = tid >> 5;

    __shared__ float4 sgc[G_N];                  // compacted gt corners
    __shared__ float sga[G_N];                   // compacted area_g + eps
    __shared__ int sgid[G_N];                    // compacted -> original gt id
    __shared__ int scnt;

    if (tid == 0) scnt = 0;
    __syncthreads();

    if (tid < G_N) {
        if (classes[b * G_N + tid] != -1) {
            const float* gb = bboxes + (b * G_N + tid) * 4;
            float x1 = gb[0], y1 = gb[1], x2 = gb[2], y2 = gb[3];
            float cx = (x1 + x2) * 0.5f, cy = (y1 + y2) * 0.5f;
            float w = x2 - x1, h = y2 - y1;
            float gx1 = cx - w * 0.5f, gy1 = cy - h * 0.5f;
            float gx2 = cx + w * 0.5f, gy2 = cy + h * 0.5f;
            int p = atomicAdd(&scnt, 1);         // order-independent: keyed by sgid
            sgc[p] = make_float4(gx1, gy1, gx2, gy2);
            sga[p] = (gx2 - gx1) * (gy2 - gy1) + 1e-16f;
            sgid[p] = tid;
        }
    }
    __syncthreads();
    const int nv = scnt;

    const int base = c * CH;
    float px1[NA], py1[NA], px2[NA], py2[NA], pap[NA];
    float bce = 0.0f;

#pragma unroll
    for (int i = 0; i < NA; i++) {
        int a = base + tid + i * NTHR;
        bool ok = a < A_N;                       // only the last chunk is ragged
        int al = ok ? a : 0;
        const float* row = pred + (long long)(b * A_N + al) * 14;
        float2 p01 = *(const float2*)(row);
        float2 p23 = *(const float2*)(row + 2);
        float conf = row[4];
        float cx = p01.x, cy = p01.y, w = p23.x, h = p23.y;
        float x1 = cx - w * 0.5f, x2 = cx + w * 0.5f;
        float y1 = cy - h * 0.5f, y2 = cy + h * 0.5f;
        float ap = (x2 - x1) * (y2 - y1);
        if (!ok) { x1 = 3.0e38f; x2 = 3.0e38f; y1 = 3.0e38f; y2 = 3.0e38f; ap = 0.0f; }
        px1[i] = x1; px2[i] = x2; py1[i] = y1; py2[i] = y2; pap[i] = ap;
        if (ok) bce += -clog(1.0f - conf);
    }

    const int wc = c * 2 + warp;
    const unsigned lowk = 0xFFFFFFFFu - (unsigned)wc;   // max-key tie -> smallest wc

    for (int j = 0; j < nv; j++) {
        float4 gq = sgc[j];                      // one LDS.128
        float age = sga[j];                      // one LDS.32
        float br;
#pragma unroll
        for (int i = 0; i < NA; i++) {
            float iw = fmaxf(fminf(px2[i], gq.z) - fmaxf(px1[i], gq.x), 0.0f);
            float ih = fminf(py2[i], gq.w) - fmaxf(py1[i], gq.y);   // no clamp
            float inter = iw * ih;
            float S = pap[i] + age;
            float r = __fdividef(inter, S);      // MUFU.RCP + FMUL
            br = (i == 0) ? r : fmaxf(br, r);    // pure max chain, no selects
        }
        br = fmaxf(br, 0.0f);                    // +0: bit order == float order
        unsigned m = __reduce_max_sync(0xFFFFFFFFu, __float_as_uint(br));
        if (lane == 0)
            g_rmax[(b * G_N + sgid[j]) * NWC + wc] = ((unsigned long long)m << 32) | lowk;
    }

    // Deterministic per-warp bce0 partial sum -> global (fixed tree order).
#pragma unroll
    for (int s = 16; s; s >>= 1) bce += __shfl_xor_sync(0xFFFFFFFFu, bce, s);
    if (lane == 0) g_bce[b * NWC + wc] = bce;
}

// Kernel 2: one block (1024 thr) per batch; one warp per gt. Combine 84 warp-chunk
// keys, rescan the winning 128-anchor warp-chunk to recover the argmax index
// (exact same arithmetic + strict-> / min-offset tie-break), then the loss.
__global__ __launch_bounds__(1024) void yolo_k2(const float* __restrict__ pred,
                                                const float* __restrict__ bboxes,
                                                const int* __restrict__ classes) {
    const int b = blockIdx.x, tid = threadIdx.x;
    const int lane = tid & 31, warp = tid >> 5;
    __shared__ float stot;
    __shared__ float sper[G_N];
    __shared__ int svalid[G_N];

    if (warp == 0) {                             // tot0 = sum of 84 bce partials
        const float* bp = g_bce + b * NWC;
        float t = bp[lane] + bp[lane + 32];
        if (lane < NWC - 64) t += bp[lane + 64];
#pragma unroll
        for (int s = 16; s; s >>= 1) t += __shfl_xor_sync(0xFFFFFFFFu, t, s);
        if (lane == 0) stot = t;
    }
    __syncthreads();
    const float tot0 = stot;

    for (int g = warp; g < G_N; g += 32) {
        int cls = classes[b * G_N + g];
        if (cls == -1) {
            if (lane == 0) { sper[g] = 0.0f; svalid[g] = 0; }
            continue;
        }
        // Combine the 84 keys (coalesced); tie -> smallest wc via ~wc low word.
        const unsigned long long* kp = g_rmax + (size_t)(b * G_N + g) * NWC;
        unsigned long long k = kp[lane];
        { unsigned long long v = kp[lane + 32]; k = v > k ? v : k; }
        if (lane < NWC - 64) { unsigned long long v = kp[lane + 64]; k = v > k ? v : k; }
#pragma unroll
        for (int s = 16; s; s >>= 1) {
            unsigned long long o = __shfl_xor_sync(0xFFFFFFFFu, k, s);
            k = o > k ? o : k;
        }
        unsigned wc = 0xFFFFFFFFu - (unsigned)(k & 0xFFFFFFFFULL);
        int cc = (int)(wc >> 1), w = (int)(wc & 1);

        // gt geometry (same math as k1's prologue)
        const float* gb = bboxes + (b * G_N + g) * 4;
        float bx1 = gb[0], by1 = gb[1], bx2 = gb[2], by2 = gb[3];
        float gcx = (bx1 + bx2) * 0.5f, gcy = (by1 + by2) * 0.5f;
        float gw = bx2 - bx1, gh = by2 - by1;
        float gx1 = gcx - gw * 0.5f, gy1 = gcy - gh * 0.5f;
        float gx2 = gcx + gw * 0.5f, gy2 = gcy + gh * 0.5f;
        float age = (gx2 - gx1) * (gy2 - gy1) + 1e-16f;

        // Rescan the winning 128-anchor warp-chunk (anchor a = cc*CH + w*32 + lane + i*64).
        int abase = cc * CH + w * 32 + lane;
        float br = -3.0e38f;
        int bidx = abase;
#pragma unroll
        for (int i = 0; i < NA; i++) {
            int a = abase + i * NTHR;
            bool ok = a < A_N;
            int al = ok ? a : 0;
            const float* row = pred + (long long)(b * A_N + al) * 14;
            float2 p01 = *(const float2*)(row);
            float2 p23 = *(const float2*)(row + 2);
            float cx = p01.x, cy = p01.y, ww = p23.x, hh = p23.y;
            float x1 = cx - ww * 0.5f, x2 = cx + ww * 0.5f;
            float y1 = cy - hh * 0.5f, y2 = cy + hh * 0.5f;
            float ap = (x2 - x1) * (y2 - y1);
            float iw = fmaxf(fminf(x2, gx2) - fmaxf(x1, gx1), 0.0f);
            float ih = fminf(y2, gy2) - fmaxf(y1, gy1);
            float inter = iw * ih;
            float S = ap + age;
            float r = __fdividef(inter, S);
            if (!ok) r = -3.0e38f;               // pads can never be selected (OOB guard)
            bool better = (i == 0) ? ok || true : (r > br);
            if (i == 0) { br = r; }
            else if (better) { br = r; bidx = a; }
        }
        unsigned rb = __float_as_uint(fmaxf(br, 0.0f));
        unsigned m2 = __reduce_max_sync(0xFFFFFFFFu, rb);
        unsigned offk = (rb == m2) ? (unsigned)bidx : 0xFFFFFFFFu;
        unsigned aidx = __reduce_min_sync(0xFFFFFFFFu, offk);   // smallest tied index

        if (lane == 0) {
            const float* row = pred + (long long)(b * A_N + aidx) * 14;
            float d0 = row[0] - gcx, d1 = row[1] - gcy;
            float d2 = row[2] - gw,  d3 = row[3] - gh;
            float coord = 5.0f * ((d0 * d0 + d1 * d1) + (d2 * d2 + d3 * d3));
            float conf = row[4];
            float conf_obj = -clog(conf);
            float clsl = 0.0f;
#pragma unroll
            for (int ccl = 0; ccl < C_N; ccl++) {
                float p = row[5 + ccl];
                clsl += (ccl == cls) ? -clog(p) : -clog(1.0f - p);
            }
            float bce0b = -clog(1.0f - conf);
            float noobj = 0.5f * (tot0 - bce0b);
            sper[g] = (coord + conf_obj) + (clsl + noobj);
            svalid[g] = 1;
        }
    }
    __syncthreads();

    if (warp == 0) {                             // per_img (fixed-order shuffle tree)
        float s = (lane < G_N ? sper[lane] : 0.0f)
                + (lane + 32 < G_N ? sper[lane + 32] : 0.0f);
        int hv = (lane < G_N ? svalid[lane] : 0)
               | (lane + 32 < G_N ? svalid[lane + 32] : 0);
#pragma unroll
        for (int s2 = 16; s2; s2 >>= 1) s += __shfl_xor_sync(0xFFFFFFFFu, s, s2);
        unsigned anyv = __ballot_sync(0xFFFFFFFFu, hv);
        if (lane == 0) g_perimg[b] = anyv ? s : 0.5f * tot0;
    }
}

// Kernel 3: deterministic final sum (warp tree).
__global__ void yolo_k3(float* __restrict__ out) {
    const int tid = threadIdx.x, lane = tid & 31, warp = tid >> 5;
    __shared__ float sp[2];
    float v = g_perimg[tid];            // 64 threads, 64 batches
#pragma unroll
    for (int s = 16; s; s >>= 1) v += __shfl_xor_sync(0xFFFFFFFFu, v, s);
    if (lane == 0) sp[warp] = v;
    __syncthreads();
    if (tid == 0) out[0] = (sp[0] + sp[1]) / (float)B_N;
}

extern "C" void kernel_launch(void* const* d_in, const int* in_sizes, int n_in,
                              void* d_out, int out_size) {
    const float* pred    = (const float*)d_in[0];
    const float* bboxes  = (const float*)d_in[1];
    const int*   classes = (const int*)d_in[2];
    float* out = (float*)d_out;

    dim3 g1(NCHUNK, B_N);
    yolo_k1<<<g1, NTHR>>>(pred, bboxes, classes);
    yolo_k2<<<B_N, 1024>>>(pred, bboxes, classes);
    yolo_k3<<<1, 64>>>(out);
}